// round 12
// baseline (speedup 1.0000x reference)
#include <cuda_runtime.h>
#include <math.h>

#define EPSF 1e-6f
#define TPB 128

__device__ float g_part[8192];
__device__ unsigned int g_ticket;   // zero-init; self-resets each launch

__global__ __launch_bounds__(TPB, 14)
void rotated_iou_loss_kernel(const float* __restrict__ pred,
                             const float* __restrict__ target,
                             const float* __restrict__ weight,
                             float* __restrict__ out,
                             int n, float inv_n)
{
    // One pool, two lives: staging (10*TPB floats) then clip buffers
    // (float2 [slot][tid], 6 + 8 slots). Conflict-free in both lives.
    __shared__ __align__(16) char pool[14 * TPB * sizeof(float2)];
    float* sIn = (float*)pool;

    int tid = threadIdx.x;
    int i = blockIdx.x * TPB + tid;

    {   // coalesced staging
        int base = blockIdx.x * TPB * 5;
        int n5 = 5 * n;
        #pragma unroll
        for (int c = 0; c < 5; c++) {
            int k = tid + c * TPB;
            int g = base + k;
            bool ok = g < n5;
            sIn[k]           = ok ? pred[g]   : 0.0f;
            sIn[5 * TPB + k] = ok ? target[g] : 0.0f;
        }
    }
    __syncthreads();

    int r5 = tid * 5;   // stride-5 smem reads: gcd(5,32)=1 -> conflict-free
    float p_x = sIn[r5+0], p_y = sIn[r5+1], p_w = sIn[r5+2],
          p_h = sIn[r5+3], p_a = sIn[r5+4];
    float t_x = sIn[5*TPB+r5+0], t_y = sIn[5*TPB+r5+1], t_w = sIn[5*TPB+r5+2],
          t_h = sIn[5*TPB+r5+3], t_a = sIn[5*TPB+r5+4];
    __syncthreads();   // staging dead -> pool becomes clip buffers

    float2* pB = (float2*)pool + tid;              // x-slab output, <=6 slots
    float2* pC = (float2*)pool + 6 * TPB + tid;    // y-slab output, <=8 slots

    float loss = 0.0f;
    if (i < n) {
        float tc, ts, cd, sd;
        __sincosf(t_a, &ts, &tc);
        __sincosf(p_a - t_a, &sd, &cd);

        float rx = p_x - t_x, ry = p_y - t_y;
        float cu =  rx * tc + ry * ts;
        float cv = -rx * ts + ry * tc;

        // Pred quad (CCW, reference corner order) in target frame.
        const float dxs[4] = { 0.5f, -0.5f, -0.5f,  0.5f };
        const float dys[4] = { 0.5f,  0.5f, -0.5f, -0.5f };
        float qx[4], qy[4];
        #pragma unroll
        for (int j = 0; j < 4; j++) {
            float lx = p_w * dxs[j], ly = p_h * dys[j];
            qx[j] = cu + lx * cd - ly * sd;
            qy[j] = cv + lx * sd + ly * cd;
        }

        float hw = t_w * 0.5f, hh = t_h * 0.5f;

        // ---- Stage 1: x-slab |x| <= hw (registers -> pB) ----
        float2* curB = pB;
        #pragma unroll
        for (int j = 0; j < 4; j++) {
            float px = qx[j],         py = qy[j];
            float cx = qx[(j+1) & 3], cy = qy[(j+1) & 3];
            bool pL = px < -hw, pH = px > hw;
            bool cL = cx < -hw, cH = cx > hw;
            float dx = cx - px, dy = cy - py;
            float inv = __fdividef(1.0f, dx);
            bool crossL = (pL != cL), crossH = (pH != cH);
            bool firstIsL = dx > 0.0f;
            #pragma unroll
            for (int e = 0; e < 2; e++) {
                bool doL = (e == 0) ? firstIsL : !firstIsL;
                bool cr  = doL ? crossL : crossH;
                if (cr) {
                    float bnd = doL ? -hw : hw;
                    float t = (bnd - px) * inv;
                    *curB = make_float2(bnd, fmaf(t, dy, py));
                    curB += TPB;
                }
            }
            if (!cL && !cH) { *curB = make_float2(cx, cy); curB += TPB; }
        }
        int m1 = (int)((curB - pB) >> 7);   // /TPB  (0 <= m1 <= 6)

        // ---- Stage 2: y-slab |y| <= hh (pB -> pC), fused sums ----
        // FIXED 6 iterations (m1 <= 6). prx=pry=0 initially makes the first
        // emission's S term exactly 0 -> no first-vertex special case; the
        // first vertex is re-read from pC[0] after the loop.
        float sx = 0.0f, sy = 0.0f, S = 0.0f;
        float prx = 0.0f, pry = 0.0f;
        float2* curC = pC;

        #define EMIT(ex_, ey_) do {                                  \
            float _ex = (ex_), _ey = (ey_);                          \
            S += prx * _ey - pry * _ex;                              \
            *curC = make_float2(_ex, _ey); curC += TPB;              \
            sx += _ex; sy += _ey;                                    \
            prx = _ex; pry = _ey;                                    \
        } while (0)

        {
            int lastB = (m1 > 0) ? (m1 - 1) : 0;
            float2 prev = pB[lastB * TPB];         // one dynamic LDS.64
            float px = prev.x, py = prev.y;
            bool pLo = py < -hh, pHi = py > hh;
            #pragma unroll
            for (int j = 0; j < 6; j++) {
                bool act = j < m1;
                float2 cur = pB[j * TPB];          // immediate-offset LDS.64
                float cx = cur.x, cy = cur.y;
                bool cLo = cy < -hh, cHi = cy > hh;
                float dx = cx - px, dy = cy - py;
                float inv = __fdividef(1.0f, dy);
                bool crossL = (pLo != cLo), crossH = (pHi != cHi);
                bool firstIsL = dy > 0.0f;
                #pragma unroll
                for (int e = 0; e < 2; e++) {
                    bool doL = (e == 0) ? firstIsL : !firstIsL;
                    bool cr  = act && (doL ? crossL : crossH);
                    if (cr) {
                        float bnd = doL ? -hh : hh;
                        float t = (bnd - py) * inv;
                        EMIT(fmaf(t, dx, px), bnd);
                    }
                }
                if (act && !cLo && !cHi) EMIT(cx, cy);
                if (act) { px = cx; py = cy; pLo = cLo; pHi = cHi; }
            }
        }
        #undef EMIT
        int m2 = (int)((curC - pC) >> 7);          // 0 <= m2 <= 8
        if (m2 > 0) {
            float2 first = *pC;                    // close the cycle
            S += prx * first.y - pry * first.x;
        }

        // ---- Quirky correction: drop the branch-cut edge ----
        // Reference drops cross(p_maxang, p_minang); for a convex CCW polygon
        // that's the unique cyclic pair whose centroid-relative ORIGINAL-frame
        // y flips >=0 -> <0. FIXED 8 iterations, immediate-offset loads.
        float inter = 0.0f;
        if (m2 >= 3) {
            float invc = __fdividef(1.0f, (float)m2);
            float mx = sx * invc, my = sy * invc;
            float wcy = mx * ts + my * tc;   // centroid's original-frame y

            float ax = mx, ay = my, bx = mx, by = my;  // default -> corr = 0
            float2 last = pC[(m2 - 1) * TPB];          // one dynamic LDS.64
            float ppx = last.x, ppy = last.y;
            float wyp = last.x * ts + last.y * tc;
            #pragma unroll
            for (int j = 0; j < 8; j++) {
                bool act = j < m2;
                float2 v = pC[j * TPB];                // immediate-offset
                float wy = v.x * ts + v.y * tc;
                if (act && wyp >= wcy && wy < wcy) {
                    ax = ppx; ay = ppy; bx = v.x; by = v.y;
                }
                if (act) { ppx = v.x; ppy = v.y; wyp = wy; }
            }

            float qax = ax - mx, qay = ay - my;
            float qbx = bx - mx, qby = by - my;
            float quirky = S - (qax * qby - qay * qbx);
            inter = 0.5f * fabsf(quirky);
        }

        float uni = p_w * p_h + t_w * t_h - inter;
        float iou = __fdividef(inter, fmaxf(uni, EPSF));
        iou = fmaxf(iou, EPSF);
        loss = (1.0f - iou * iou * iou) * weight[i];
    }

    // ---- block reduction -> per-block partial (deterministic) ----
    #pragma unroll
    for (int o = 16; o > 0; o >>= 1)
        loss += __shfl_down_sync(0xffffffffu, loss, o);

    __shared__ float warp_sums[4];
    __shared__ int is_last;
    int lane = tid & 31;
    int wid  = tid >> 5;
    if (lane == 0) warp_sums[wid] = loss;
    __syncthreads();

    if (wid == 0) {
        float v = (lane < 4) ? warp_sums[lane] : 0.0f;
        v += __shfl_down_sync(0xffffffffu, v, 2);
        v += __shfl_down_sync(0xffffffffu, v, 1);
        if (lane == 0) {
            g_part[blockIdx.x] = v;
            __threadfence();
            unsigned int t = atomicAdd(&g_ticket, 1u);
            is_last = (t == gridDim.x - 1) ? 1 : 0;
        }
    }
    __syncthreads();

    // ---- last block: fixed-order final reduction ----
    if (is_last) {
        int nb = gridDim.x;
        double s = 0.0;
        for (int b = tid; b < nb; b += TPB)
            s += (double)g_part[b];
        #pragma unroll
        for (int o = 16; o > 0; o >>= 1)
            s += __shfl_down_sync(0xffffffffu, s, o);
        __shared__ double dsum[4];
        if (lane == 0) dsum[wid] = s;
        __syncthreads();
        if (wid == 0) {
            double v = (lane < 4) ? dsum[lane] : 0.0;
            v += __shfl_down_sync(0xffffffffu, v, 2);
            v += __shfl_down_sync(0xffffffffu, v, 1);
            if (lane == 0) {
                out[0] = (float)(v * (double)inv_n);
                g_ticket = 0u;
            }
        }
    }
}

extern "C" void kernel_launch(void* const* d_in, const int* in_sizes, int n_in,
                              void* d_out, int out_size) {
    const float* pred   = (const float*)d_in[0];
    const float* target = (const float*)d_in[1];
    const float* wgt    = (const float*)d_in[2];
    float* out = (float*)d_out;

    int n = in_sizes[2];
    if (n * 5 != in_sizes[0]) n = in_sizes[0] / 5;

    int blocks = (n + TPB - 1) / TPB;   // 500k -> 3907 (< 8192)

    rotated_iou_loss_kernel<<<blocks, TPB>>>(pred, target, wgt, out,
                                             n, 1.0f / (float)n);
}

// round 13
// speedup vs baseline: 1.0275x; 1.0275x over previous
#include <cuda_runtime.h>
#include <math.h>

#define EPSF 1e-6f
#define TPB 128

__device__ float g_part[8192];
__device__ unsigned int g_ticket;   // zero-init; self-resets each launch

__global__ __launch_bounds__(TPB, 14)
void rotated_iou_loss_kernel(const float* __restrict__ pred,
                             const float* __restrict__ target,
                             const float* __restrict__ weight,
                             float* __restrict__ out,
                             int n, float inv_n)
{
    // Pool: 15 float2-slots per thread.
    //   life 1: staging (10*TPB floats = 5 slots)
    //   life 2: B = slots 0..5 (x-slab), C = slots 6..13 (y-slab),
    //           slot 14 = spare for the trailing unconditional store.
    __shared__ __align__(16) char pool[15 * TPB * sizeof(float2)];
    float* sIn = (float*)pool;

    int tid = threadIdx.x;
    int i = blockIdx.x * TPB + tid;

    {   // coalesced staging
        int base = blockIdx.x * TPB * 5;
        int n5 = 5 * n;
        #pragma unroll
        for (int c = 0; c < 5; c++) {
            int k = tid + c * TPB;
            int g = base + k;
            bool ok = g < n5;
            sIn[k]           = ok ? pred[g]   : 0.0f;
            sIn[5 * TPB + k] = ok ? target[g] : 0.0f;
        }
    }
    __syncthreads();

    int r5 = tid * 5;   // stride-5 smem reads: gcd(5,32)=1 -> conflict-free
    float p_x = sIn[r5+0], p_y = sIn[r5+1], p_w = sIn[r5+2],
          p_h = sIn[r5+3], p_a = sIn[r5+4];
    float t_x = sIn[5*TPB+r5+0], t_y = sIn[5*TPB+r5+1], t_w = sIn[5*TPB+r5+2],
          t_h = sIn[5*TPB+r5+3], t_a = sIn[5*TPB+r5+4];
    __syncthreads();   // staging dead -> pool becomes clip buffers

    float2* pB = (float2*)pool + tid;              // slots 0..5
    float2* pC = (float2*)pool + 6 * TPB + tid;    // slots 6..13 (+14 spare)

    float loss = 0.0f;
    if (i < n) {
        float tc, ts, cd, sd;
        __sincosf(t_a, &ts, &tc);
        __sincosf(p_a - t_a, &sd, &cd);

        float rx = p_x - t_x, ry = p_y - t_y;
        float cu =  rx * tc + ry * ts;
        float cv = -rx * ts + ry * tc;

        // Pred quad (CCW, reference corner order) in target frame.
        const float dxs[4] = { 0.5f, -0.5f, -0.5f,  0.5f };
        const float dys[4] = { 0.5f,  0.5f, -0.5f, -0.5f };
        float qx[4], qy[4];
        #pragma unroll
        for (int j = 0; j < 4; j++) {
            float lx = p_w * dxs[j], ly = p_h * dys[j];
            qx[j] = cu + lx * cd - ly * sd;
            qy[j] = cv + lx * sd + ly * cd;
        }

        float hw = t_w * 0.5f, hh = t_h * 0.5f;

        // ---- Stage 1: x-slab |x| <= hw (registers -> pB) ----
        // Branch-free: stores unconditional, pointer advances predicated.
        // Non-advancing stores leave garbage that the next real emit (or a
        // masked read) overwrites/ignores.
        float2* curB = pB;
        #pragma unroll
        for (int j = 0; j < 4; j++) {
            float px = qx[j],         py = qy[j];
            float cx = qx[(j+1) & 3], cy = qy[(j+1) & 3];
            bool pL = px < -hw, pH = px > hw;
            bool cL = cx < -hw, cH = cx > hw;
            float dx = cx - px, dy = cy - py;
            float inv = __fdividef(1.0f, dx);
            bool crossL = (pL != cL), crossH = (pH != cH);
            bool firstIsL = dx > 0.0f;
            #pragma unroll
            for (int e = 0; e < 2; e++) {
                bool doL = (e == 0) ? firstIsL : !firstIsL;
                bool cr  = doL ? crossL : crossH;
                float bnd = doL ? -hw : hw;
                float t = (bnd - px) * inv;
                *curB = make_float2(bnd, fmaf(t, dy, py));   // unconditional STS
                if (cr) curB += TPB;                          // predicated IADD
            }
            bool keep = !cL && !cH;
            *curB = make_float2(cx, cy);
            if (keep) curB += TPB;
        }
        int m1 = (int)((curB - pB) >> 7);   // /TPB  (0 <= m1 <= 6)

        // ---- Stage 2: y-slab |y| <= hh (pB -> pC), fused sums ----
        // FIXED 6 iterations; branch-free emission. prx=pry=0 makes the first
        // emission's S term exactly 0.
        float sx = 0.0f, sy = 0.0f, S = 0.0f;
        float prx = 0.0f, pry = 0.0f;
        float2* curC = pC;

        #define EMIT(cr_, ex_, ey_) do {                              \
            bool _c = (cr_);                                          \
            float _ex = (ex_), _ey = (ey_);                           \
            *curC = make_float2(_ex, _ey);        /* unconditional */ \
            if (_c) {                                                 \
                S += prx * _ey - pry * _ex;                           \
                sx += _ex; sy += _ey;                                 \
                prx = _ex; pry = _ey;                                 \
                curC += TPB;                                          \
            }                                                         \
        } while (0)

        {
            int lastB = (m1 > 0) ? (m1 - 1) : 0;
            float2 prev = pB[lastB * TPB];         // one dynamic LDS.64
            float px = prev.x, py = prev.y;
            bool pLo = py < -hh, pHi = py > hh;
            #pragma unroll
            for (int j = 0; j < 6; j++) {
                bool act = j < m1;
                float2 cur = pB[j * TPB];          // immediate-offset LDS.64
                float cx = cur.x, cy = cur.y;
                bool cLo = cy < -hh, cHi = cy > hh;
                float dx = cx - px, dy = cy - py;
                float inv = __fdividef(1.0f, dy);
                bool crossL = (pLo != cLo), crossH = (pHi != cHi);
                bool firstIsL = dy > 0.0f;
                #pragma unroll
                for (int e = 0; e < 2; e++) {
                    bool doL = (e == 0) ? firstIsL : !firstIsL;
                    bool cr  = act && (doL ? crossL : crossH);
                    float bnd = doL ? -hh : hh;
                    float t = (bnd - py) * inv;
                    EMIT(cr, fmaf(t, dx, px), bnd);
                }
                EMIT(act && !cLo && !cHi, cx, cy);
                if (act) { px = cx; py = cy; pLo = cLo; pHi = cHi; }
            }
        }
        #undef EMIT
        int m2 = (int)((curC - pC) >> 7);          // 0 <= m2 <= 8
        if (m2 > 0) {
            float2 first = *pC;                    // close the cycle
            S += prx * first.y - pry * first.x;
        }

        // ---- Quirky correction: drop the branch-cut edge ----
        // For a convex CCW polygon, the dropped cross(p_maxang, p_minang) is
        // the unique cyclic pair whose centroid-relative ORIGINAL-frame y
        // flips >=0 -> <0. FIXED 8 iterations, select-based tracking.
        float inter = 0.0f;
        if (m2 >= 3) {
            float invc = __fdividef(1.0f, (float)m2);
            float mx = sx * invc, my = sy * invc;
            float wcy = mx * ts + my * tc;   // centroid's original-frame y

            float ax = mx, ay = my, bx = mx, by = my;  // default -> corr = 0
            float2 last = pC[(m2 - 1) * TPB];          // one dynamic LDS.64
            float ppx = last.x, ppy = last.y;
            float wyp = last.x * ts + last.y * tc;
            #pragma unroll
            for (int j = 0; j < 8; j++) {
                bool act = j < m2;
                float2 v = pC[j * TPB];                // immediate-offset
                float wy = v.x * ts + v.y * tc;
                bool flip = act && (wyp >= wcy) && (wy < wcy);
                ax = flip ? ppx : ax;  ay = flip ? ppy : ay;
                bx = flip ? v.x : bx;  by = flip ? v.y : by;
                ppx = act ? v.x : ppx; ppy = act ? v.y : ppy;
                wyp = act ? wy  : wyp;
            }

            float qax = ax - mx, qay = ay - my;
            float qbx = bx - mx, qby = by - my;
            float quirky = S - (qax * qby - qay * qbx);
            inter = 0.5f * fabsf(quirky);
        }

        float uni = p_w * p_h + t_w * t_h - inter;
        float iou = __fdividef(inter, fmaxf(uni, EPSF));
        iou = fmaxf(iou, EPSF);
        loss = (1.0f - iou * iou * iou) * weight[i];
    }

    // ---- block reduction -> per-block partial (deterministic) ----
    #pragma unroll
    for (int o = 16; o > 0; o >>= 1)
        loss += __shfl_down_sync(0xffffffffu, loss, o);

    __shared__ float warp_sums[4];
    __shared__ int is_last;
    int lane = tid & 31;
    int wid  = tid >> 5;
    if (lane == 0) warp_sums[wid] = loss;
    __syncthreads();

    if (wid == 0) {
        float v = (lane < 4) ? warp_sums[lane] : 0.0f;
        v += __shfl_down_sync(0xffffffffu, v, 2);
        v += __shfl_down_sync(0xffffffffu, v, 1);
        if (lane == 0) {
            g_part[blockIdx.x] = v;
            __threadfence();
            unsigned int t = atomicAdd(&g_ticket, 1u);
            is_last = (t == gridDim.x - 1) ? 1 : 0;
        }
    }
    __syncthreads();

    // ---- last block: fixed-order final reduction ----
    if (is_last) {
        int nb = gridDim.x;
        double s = 0.0;
        for (int b = tid; b < nb; b += TPB)
            s += (double)g_part[b];
        #pragma unroll
        for (int o = 16; o > 0; o >>= 1)
            s += __shfl_down_sync(0xffffffffu, s, o);
        __shared__ double dsum[4];
        if (lane == 0) dsum[wid] = s;
        __syncthreads();
        if (wid == 0) {
            double v = (lane < 4) ? dsum[lane] : 0.0;
            v += __shfl_down_sync(0xffffffffu, v, 2);
            v += __shfl_down_sync(0xffffffffu, v, 1);
            if (lane == 0) {
                out[0] = (float)(v * (double)inv_n);
                g_ticket = 0u;
            }
        }
    }
}

extern "C" void kernel_launch(void* const* d_in, const int* in_sizes, int n_in,
                              void* d_out, int out_size) {
    const float* pred   = (const float*)d_in[0];
    const float* target = (const float*)d_in[1];
    const float* wgt    = (const float*)d_in[2];
    float* out = (float*)d_out;

    int n = in_sizes[2];
    if (n * 5 != in_sizes[0]) n = in_sizes[0] / 5;

    int blocks = (n + TPB - 1) / TPB;   // 500k -> 3907 (< 8192)

    rotated_iou_loss_kernel<<<blocks, TPB>>>(pred, target, wgt, out,
                                             n, 1.0f / (float)n);
}

// round 14
// speedup vs baseline: 1.0634x; 1.0349x over previous
#include <cuda_runtime.h>
#include <math.h>

#define EPSF 1e-6f
#define TPB 128

__device__ float g_part[8192];
__device__ unsigned int g_ticket;   // zero-init; self-resets each launch

__global__ __launch_bounds__(TPB, 14)
void rotated_iou_loss_kernel(const float* __restrict__ pred,
                             const float* __restrict__ target,
                             const float* __restrict__ weight,
                             float* __restrict__ out,
                             int n, float inv_n)
{
    // Pool: 15 float2-slots per thread.
    //   life 1: staging (10*TPB floats = 5 slots)
    //   life 2: B = slots 0..5 (x-slab), C = slots 6..13 (y-slab),
    //           slot 14 = spare for the trailing unconditional store.
    __shared__ __align__(16) char pool[15 * TPB * sizeof(float2)];
    float* sIn = (float*)pool;

    int tid = threadIdx.x;
    int i = blockIdx.x * TPB + tid;

    {   // coalesced float4 staging (segment = TPB*5 floats = TPB*5/4 float4s,
        // 16B-aligned because TPB*5*4 = 2560 bytes per block segment)
        const float4* p4 = (const float4*)pred;
        const float4* t4 = (const float4*)target;
        float4* s4P = (float4*)sIn;
        float4* s4T = (float4*)(sIn + 5 * TPB);
        int b4 = blockIdx.x * (TPB * 5 / 4);
        int n5 = 5 * n;
        int n4 = n5 >> 2;           // complete float4s
        #pragma unroll
        for (int k = tid; k < TPB * 5 / 4; k += TPB) {
            int g4 = b4 + k;
            float4 vp, vt;
            if (g4 < n4) {
                vp = p4[g4];
                vt = t4[g4];
            } else {                 // partial tail (last block only)
                int gf = g4 << 2;
                vp.x = (gf + 0 < n5) ? pred[gf + 0] : 0.0f;
                vp.y = (gf + 1 < n5) ? pred[gf + 1] : 0.0f;
                vp.z = (gf + 2 < n5) ? pred[gf + 2] : 0.0f;
                vp.w = (gf + 3 < n5) ? pred[gf + 3] : 0.0f;
                vt.x = (gf + 0 < n5) ? target[gf + 0] : 0.0f;
                vt.y = (gf + 1 < n5) ? target[gf + 1] : 0.0f;
                vt.z = (gf + 2 < n5) ? target[gf + 2] : 0.0f;
                vt.w = (gf + 3 < n5) ? target[gf + 3] : 0.0f;
            }
            s4P[k] = vp;
            s4T[k] = vt;
        }
    }
    __syncthreads();

    int r5 = tid * 5;   // stride-5 smem reads: gcd(5,32)=1 -> conflict-free
    float p_x = sIn[r5+0], p_y = sIn[r5+1], p_w = sIn[r5+2],
          p_h = sIn[r5+3], p_a = sIn[r5+4];
    float t_x = sIn[5*TPB+r5+0], t_y = sIn[5*TPB+r5+1], t_w = sIn[5*TPB+r5+2],
          t_h = sIn[5*TPB+r5+3], t_a = sIn[5*TPB+r5+4];
    __syncthreads();   // staging dead -> pool becomes clip buffers

    float2* pB = (float2*)pool + tid;              // slots 0..5
    float2* pC = (float2*)pool + 6 * TPB + tid;    // slots 6..13 (+14 spare)

    float loss = 0.0f;
    if (i < n) {
        float tc, ts, cd, sd;
        __sincosf(t_a, &ts, &tc);
        __sincosf(p_a - t_a, &sd, &cd);

        float rx = p_x - t_x, ry = p_y - t_y;
        float cu =  rx * tc + ry * ts;
        float cv = -rx * ts + ry * tc;

        // Pred quad (CCW, reference corner order) in target frame.
        const float dxs[4] = { 0.5f, -0.5f, -0.5f,  0.5f };
        const float dys[4] = { 0.5f,  0.5f, -0.5f, -0.5f };
        float qx[4], qy[4];
        #pragma unroll
        for (int j = 0; j < 4; j++) {
            float lx = p_w * dxs[j], ly = p_h * dys[j];
            qx[j] = cu + lx * cd - ly * sd;
            qy[j] = cv + lx * sd + ly * cd;
        }

        float hw = t_w * 0.5f, hh = t_h * 0.5f;

        // ---- Stage 1: x-slab |x| <= hw (registers -> pB), branch-free ----
        float2* curB = pB;
        #pragma unroll
        for (int j = 0; j < 4; j++) {
            float px = qx[j],         py = qy[j];
            float cx = qx[(j+1) & 3], cy = qy[(j+1) & 3];
            bool pL = px < -hw, pH = px > hw;
            bool cL = cx < -hw, cH = cx > hw;
            float dx = cx - px, dy = cy - py;
            float inv = __fdividef(1.0f, dx);
            bool crossL = (pL != cL), crossH = (pH != cH);
            bool firstIsL = dx > 0.0f;
            #pragma unroll
            for (int e = 0; e < 2; e++) {
                bool doL = (e == 0) ? firstIsL : !firstIsL;
                bool cr  = doL ? crossL : crossH;
                float bnd = doL ? -hw : hw;
                float t = (bnd - px) * inv;
                *curB = make_float2(bnd, fmaf(t, dy, py));   // unconditional STS
                if (cr) curB += TPB;                          // predicated IADD
            }
            bool keep = !cL && !cH;
            *curB = make_float2(cx, cy);
            if (keep) curB += TPB;
        }
        int m1 = (int)((curB - pB) >> 7);   // /TPB  (0 <= m1 <= 6)

        // ---- Stage 2: y-slab |y| <= hh (pB -> pC), fused sums ----
        float sx = 0.0f, sy = 0.0f, S = 0.0f;
        float prx = 0.0f, pry = 0.0f;
        float2* curC = pC;

        #define EMIT(cr_, ex_, ey_) do {                              \
            bool _c = (cr_);                                          \
            float _ex = (ex_), _ey = (ey_);                           \
            *curC = make_float2(_ex, _ey);        /* unconditional */ \
            if (_c) {                                                 \
                S += prx * _ey - pry * _ex;                           \
                sx += _ex; sy += _ey;                                 \
                prx = _ex; pry = _ey;                                 \
                curC += TPB;                                          \
            }                                                         \
        } while (0)

        {
            int lastB = (m1 > 0) ? (m1 - 1) : 0;
            float2 prev = pB[lastB * TPB];         // one dynamic LDS.64
            float px = prev.x, py = prev.y;
            bool pLo = py < -hh, pHi = py > hh;
            #pragma unroll
            for (int j = 0; j < 6; j++) {
                bool act = j < m1;
                float2 cur = pB[j * TPB];          // immediate-offset LDS.64
                float cx = cur.x, cy = cur.y;
                bool cLo = cy < -hh, cHi = cy > hh;
                float dx = cx - px, dy = cy - py;
                float inv = __fdividef(1.0f, dy);
                bool crossL = (pLo != cLo), crossH = (pHi != cHi);
                bool firstIsL = dy > 0.0f;
                #pragma unroll
                for (int e = 0; e < 2; e++) {
                    bool doL = (e == 0) ? firstIsL : !firstIsL;
                    bool cr  = act && (doL ? crossL : crossH);
                    float bnd = doL ? -hh : hh;
                    float t = (bnd - py) * inv;
                    EMIT(cr, fmaf(t, dx, px), bnd);
                }
                EMIT(act && !cLo && !cHi, cx, cy);
                if (act) { px = cx; py = cy; pLo = cLo; pHi = cHi; }
            }
        }
        #undef EMIT
        int m2 = (int)((curC - pC) >> 7);          // 0 <= m2 <= 8
        if (m2 > 0) {
            float2 first = *pC;                    // close the cycle
            S += prx * first.y - pry * first.x;
        }

        // ---- Quirky correction: drop the branch-cut edge ----
        float inter = 0.0f;
        if (m2 >= 3) {
            float invc = __fdividef(1.0f, (float)m2);
            float mx = sx * invc, my = sy * invc;
            float wcy = mx * ts + my * tc;   // centroid's original-frame y

            float ax = mx, ay = my, bx = mx, by = my;  // default -> corr = 0
            float2 last = pC[(m2 - 1) * TPB];          // one dynamic LDS.64
            float ppx = last.x, ppy = last.y;
            float wyp = last.x * ts + last.y * tc;
            #pragma unroll
            for (int j = 0; j < 8; j++) {
                bool act = j < m2;
                float2 v = pC[j * TPB];                // immediate-offset
                float wy = v.x * ts + v.y * tc;
                bool flip = act && (wyp >= wcy) && (wy < wcy);
                ax = flip ? ppx : ax;  ay = flip ? ppy : ay;
                bx = flip ? v.x : bx;  by = flip ? v.y : by;
                ppx = act ? v.x : ppx; ppy = act ? v.y : ppy;
                wyp = act ? wy  : wyp;
            }

            float qax = ax - mx, qay = ay - my;
            float qbx = bx - mx, qby = by - my;
            float quirky = S - (qax * qby - qay * qbx);
            inter = 0.5f * fabsf(quirky);
        }

        float uni = p_w * p_h + t_w * t_h - inter;
        float iou = __fdividef(inter, fmaxf(uni, EPSF));
        iou = fmaxf(iou, EPSF);
        loss = (1.0f - iou * iou * iou) * weight[i];
    }

    // ---- block reduction -> per-block partial (deterministic) ----
    #pragma unroll
    for (int o = 16; o > 0; o >>= 1)
        loss += __shfl_down_sync(0xffffffffu, loss, o);

    __shared__ float warp_sums[4];
    __shared__ int is_last;
    int lane = tid & 31;
    int wid  = tid >> 5;
    if (lane == 0) warp_sums[wid] = loss;
    __syncthreads();

    if (wid == 0) {
        float v = (lane < 4) ? warp_sums[lane] : 0.0f;
        v += __shfl_down_sync(0xffffffffu, v, 2);
        v += __shfl_down_sync(0xffffffffu, v, 1);
        if (lane == 0) {
            g_part[blockIdx.x] = v;
            __threadfence();
            unsigned int t = atomicAdd(&g_ticket, 1u);
            is_last = (t == gridDim.x - 1) ? 1 : 0;
        }
    }
    __syncthreads();

    // ---- last block: fixed-order final reduction (float4 loads) ----
    if (is_last) {
        int nb = gridDim.x;
        int nb4 = nb >> 2;
        const float4* gp4 = (const float4*)g_part;
        double s = 0.0;
        for (int b = tid; b < nb4; b += TPB) {
            float4 v = gp4[b];
            s += (double)v.x + (double)v.y + (double)v.z + (double)v.w;
        }
        for (int b = (nb4 << 2) + tid; b < nb; b += TPB)
            s += (double)g_part[b];
        #pragma unroll
        for (int o = 16; o > 0; o >>= 1)
            s += __shfl_down_sync(0xffffffffu, s, o);
        __shared__ double dsum[4];
        if (lane == 0) dsum[wid] = s;
        __syncthreads();
        if (wid == 0) {
            double v = (lane < 4) ? dsum[lane] : 0.0;
            v += __shfl_down_sync(0xffffffffu, v, 2);
            v += __shfl_down_sync(0xffffffffu, v, 1);
            if (lane == 0) {
                out[0] = (float)(v * (double)inv_n);
                g_ticket = 0u;
            }
        }
    }
}

extern "C" void kernel_launch(void* const* d_in, const int* in_sizes, int n_in,
                              void* d_out, int out_size) {
    const float* pred   = (const float*)d_in[0];
    const float* target = (const float*)d_in[1];
    const float* wgt    = (const float*)d_in[2];
    float* out = (float*)d_out;

    int n = in_sizes[2];
    if (n * 5 != in_sizes[0]) n = in_sizes[0] / 5;

    int blocks = (n + TPB - 1) / TPB;   // 500k -> 3907 (< 8192)

    rotated_iou_loss_kernel<<<blocks, TPB>>>(pred, target, wgt, out,
                                             n, 1.0f / (float)n);
}